// round 12
// baseline (speedup 1.0000x reference)
#include <cuda_runtime.h>
#include <cuda_fp16.h>
#include <cstdint>
#include <math.h>

// ---------------- problem constants ----------------
#define C_DIM   256
#define M_CLS   256
#define HW      16384
#define N_PIX   262144
#define TILE_P  128                    // pixels per GROUP-tile
#define KB      32                     // channels per A chunk
#define NKS     (C_DIM / KB)           // 8
#define NTASKS  (N_PIX / TILE_P)       // 2048
#define NTHREADS 512                   // 2 groups x 256
#define GRID     152                   // persistent: one CTA per SM
#define NGROUPS  (GRID * 2)            // 304 independent task streams
#define SCALE_EX2 20.60992915555662f   // (1/0.07) * log2(e)

// ---------------- smem layout (bytes) ----------------
#define SM_B       0
#define B_BYTES    (M_CLS * C_DIM * 2)     // 131072 (shared by both groups)
#define A_BUF      (TILE_P * 64)           // 8192 per buffer (128px x 32ch f16)
#define SM_A_BASE  (B_BYTES)               // + g*16384 + buf*8192
#define SM_RED_B   (SM_A_BASE + 4 * A_BUF) // 163840; per group 4640B
#define SM_FIN     (SM_RED_B + 2 * 4640)   // 173120 -> align to 173184
#define SMEM_BYTES (173184 + 3072 + 64)    // 176320

__device__ double g_sum[NGROUPS];
__device__ float  g_cnt[NGROUPS];
__device__ __align__(16) __half g_queue_h[M_CLS * C_DIM];
__device__ unsigned int g_done;   // zero-init; reset by winning group each launch

__device__ __forceinline__ uint32_t smem_u32(const void* p) {
    uint32_t a;
    asm("{ .reg .u64 t; cvta.to.shared.u64 t, %1; cvt.u32.u64 %0, t; }" : "=r"(a) : "l"(p));
    return a;
}
__device__ __forceinline__ uint32_t pkh2(float x, float y) {
    __half2 h = __floats2half2_rn(x, y);
    return *(uint32_t*)&h;
}
__device__ __forceinline__ float ex2(float x) {
    float r;
    asm("ex2.approx.f32 %0, %1;" : "=f"(r) : "f"(x));
    return r;
}
#define BARG(id) asm volatile("bar.sync %0, 256;" :: "r"(id) : "memory")
#define CP_ASYNC16(dst, src) \
    asm volatile("cp.async.cg.shared.global [%0], [%1], 16;" :: "r"(dst), "l"(src) : "memory")
#define CP_COMMIT()  asm volatile("cp.async.commit_group;" ::: "memory")
#define CP_WAIT0()   asm volatile("cp.async.wait_group 0;" ::: "memory")

#define LDMATRIX_X4(r0, r1, r2, r3, addr) \
    asm volatile("ldmatrix.sync.aligned.m8n8.x4.shared.b16 {%0,%1,%2,%3}, [%4];" \
                 : "=r"(r0), "=r"(r1), "=r"(r2), "=r"(r3) : "r"(addr))

// f16 x f16 + f16 MMA: D/C are 2 regs of f16x2
#define MMAF16(c, a0, a1, a2, a3, b0, b1) \
    asm volatile("mma.sync.aligned.m16n8k16.row.col.f16.f16.f16.f16 " \
                 "{%0,%1}, {%2,%3,%4,%5}, {%6,%7}, {%0,%1};" \
                 : "+r"((c)[0]), "+r"((c)[1]) \
                 : "r"(a0), "r"(a1), "r"(a2), "r"(a3), "r"(b0), "r"(b1))

// ---- pre-pass: queue f32 -> f16 ----
__global__ void queue_to_f16_kernel(const float* __restrict__ queue)
{
    int i = (blockIdx.x * blockDim.x + threadIdx.x) * 2;
    float2 v = *(const float2*)(queue + i);
    *(__half2*)(g_queue_h + i) = __floats2half2_rn(v.x, v.y);
}

// ---- main: persistent; 2 independent 256-thread groups share one B tile ----
__global__ __launch_bounds__(NTHREADS, 1)
void pcl_main_kernel(const float* __restrict__ feats,
                     const int*   __restrict__ labels,
                     float*       __restrict__ out)
{
    extern __shared__ char smem[];
    __shared__ bool s_last[2];
    const uint32_t sb  = smem_u32(smem);
    const int tid  = threadIdx.x;
    const int g    = tid >> 8;          // group 0/1
    const int tig  = tid & 255;         // thread-in-group
    const int warp = tig >> 5;          // 0..7 within group
    const int lane = tid & 31;
    const int barid = 1 + g;

    // ---- B staging ONCE (whole CTA): 128KB f16 queue, class-permuted + swizzled ----
    // Within each 64-class group: physical p6 = 16t + 2ni + e stored at logical
    // slot 8ni + 2t + e  ->  a thread's 16 epilogue classes are contiguous.
    {
        #pragma unroll
        for (int i = 0; i < 16; i++) {
            int q    = tid + NTHREADS * i;       // 0..8191 16B-chunks
            int cls  = q >> 5;                   // physical class
            int c    = q & 31;
            int p6   = cls & 63;
            int slot = (((p6 >> 1) & 7) << 3) | (((p6 >> 4) & 3) << 1) | (p6 & 1);
            int lrow = (cls & ~63) | slot;       // logical smem row
            uint32_t dst = sb + SM_B + lrow * 512 + ((c ^ (lrow & 7)) << 4);
            const void* src = (const char*)g_queue_h + cls * 512 + c * 16;
            CP_ASYNC16(dst, src);
        }
        CP_COMMIT();
    }

    // ---- A staging roles (per group): pix = tig&127, cg = tig>>7 (16 ch) ----
    const int pixA = tig & 127;
    const int cg   = tig >> 7;          // 0/1: channels cg*16 .. +15
    const uint32_t smA[2] = { sb + SM_A_BASE + (uint32_t)g * 2 * A_BUF,
                              sb + SM_A_BASE + (uint32_t)g * 2 * A_BUF + A_BUF };
    const uint32_t a_st_off0 = pixA * 64 + (((uint32_t)(cg * 2 + 0) ^ ((pixA >> 1) & 3)) << 4);
    const uint32_t a_st_off1 = pixA * 64 + (((uint32_t)(cg * 2 + 1) ^ ((pixA >> 1) & 3)) << 4);

    uint32_t areg[8];   // 16 channels packed as f16x2
    auto loadA = [&](const float* fb, int ks) {
        #pragma unroll
        for (int j = 0; j < 8; j++) {
            float x = __ldg(fb + (size_t)(ks * KB + cg * 16 + 2 * j) * HW + pixA);
            float y = __ldg(fb + (size_t)(ks * KB + cg * 16 + 2 * j + 1) * HW + pixA);
            areg[j] = pkh2(x, y);
        }
    };
    auto storeA = [&](uint32_t abase) {
        asm volatile("st.shared.v4.b32 [%0], {%1,%2,%3,%4};"
                     :: "r"(abase + a_st_off0), "r"(areg[0]), "r"(areg[1]), "r"(areg[2]), "r"(areg[3]) : "memory");
        asm volatile("st.shared.v4.b32 [%0], {%1,%2,%3,%4};"
                     :: "r"(abase + a_st_off1), "r"(areg[4]), "r"(areg[5]), "r"(areg[6]), "r"(areg[7]) : "memory");
    };

    // ---- warp tiling per group: 8 warps = 2(pix) x 4(cls); warp tile 64x64 ----
    const int wm = warp & 1;
    const int wn = warp >> 1;

    const int arow0 = wm * 64 + (lane & 15);
    const int ksel  = lane >> 4;
    const uint32_t abase_off = (uint32_t)(arow0 * 64);
    const uint32_t aswz      = (uint32_t)((arow0 >> 1) & 3);

    const int bg   = lane & 7;
    const int bsel = lane >> 3;
    const int bofs = bg + ((bsel >= 2) ? 8 : 0);
    const int bkh  = bsel & 1;

    const int gq = lane >> 2;
    const int t  = lane & 3;
    float* red_sn = (float*)(smem + SM_RED_B + g * 4640);          // [4][128]
    float* red_sp = (float*)(smem + SM_RED_B + g * 4640 + 2048);   // [4][128]
    float* wpart  = (float*)(smem + SM_RED_B + g * 4640 + 4096);   // [8]

    double acc_s = 0.0;
    float  acc_c = 0.0f;

    // ---- prologue for first task ----
    const int gid = blockIdx.x * 2 + g;
    int task = gid;
    const float* fbase = feats + (size_t)((task * TILE_P) / HW) * C_DIM * HW
                               + ((task * TILE_P) % HW);
    loadA(fbase, 0);
    storeA(smA[0]);
    CP_WAIT0();
    __syncthreads();   // B visible + both groups' first A staged; last CTA-wide sync

    // ---- persistent task loop (group-independent from here on) ----
    #pragma unroll 1
    for (; task < NTASKS; task += NGROUPS) {
        const int pix0 = task * TILE_P;
        const int next_task = task + NGROUPS;
        const float* fbase_next =
            (next_task < NTASKS)
                ? feats + (size_t)((next_task * TILE_P) / HW) * C_DIM * HW
                        + ((next_task * TILE_P) % HW)
                : fbase;

        uint32_t acc[4][8][2];   // f16x2 accumulators
        #pragma unroll
        for (int mi = 0; mi < 4; mi++)
            #pragma unroll
            for (int ni = 0; ni < 8; ni++) {
                acc[mi][ni][0] = 0u;
                acc[mi][ni][1] = 0u;
            }

        // ---- mainloop: 8 chunks, double-buffered A, cross-task prefetch ----
        #pragma unroll 1
        for (int ks = 0; ks < NKS; ks++) {
            const bool have_next = (ks < NKS - 1) || (next_task < NTASKS);
            if (ks < NKS - 1)           loadA(fbase, ks + 1);
            else if (have_next)         loadA(fbase_next, 0);

            const uint32_t acur = smA[ks & 1];
            #pragma unroll
            for (int kf = 0; kf < 2; kf++) {
                // B fragments: 4 ldmatrix.x4 (64 classes, k16)
                uint32_t bfr[4][4];
                const uint32_t kchunk = ks * 4 + kf * 2 + bkh;
                #pragma unroll
                for (int nt = 0; nt < 4; nt++) {
                    const int lcls = wn * 64 + nt * 16 + bofs;
                    uint32_t addr = sb + SM_B + lcls * 512 +
                                    ((kchunk ^ (uint32_t)(lcls & 7)) << 4);
                    LDMATRIX_X4(bfr[nt][0], bfr[nt][1], bfr[nt][2], bfr[nt][3], addr);
                }
                // A per mi (4 regs live), 8 MMAs per A fragment
                #pragma unroll
                for (int mi = 0; mi < 4; mi++) {
                    uint32_t a0, a1, a2, a3;
                    uint32_t addr = acur + abase_off + mi * 1024 +
                                    (((uint32_t)(kf * 2 + ksel) ^ aswz) << 4);
                    LDMATRIX_X4(a0, a1, a2, a3, addr);
                    #pragma unroll
                    for (int nt = 0; nt < 4; nt++) {
                        MMAF16(acc[mi][nt * 2 + 0], a0, a1, a2, a3, bfr[nt][0], bfr[nt][1]);
                        MMAF16(acc[mi][nt * 2 + 1], a0, a1, a2, a3, bfr[nt][2], bfr[nt][3]);
                    }
                }
            }

            if (have_next) {
                storeA(smA[(ks + 1) & 1]);
                BARG(barid);
            }
        }

        // ---- register epilogue: acc[mi][ni][h] = f16x2 {cols 2t, 2t+1} at
        //      pixel wm*64 + mi*16 + h*8 + gq; class wn*64 + 16t + 2ni + e ----
        #pragma unroll
        for (int mi = 0; mi < 4; mi++) {
            #pragma unroll
            for (int h = 0; h < 2; h++) {
                const int pixel = wm * 64 + mi * 16 + h * 8 + gq;
                const int4* lp = (const int4*)(labels +
                    (size_t)(pix0 + pixel) * M_CLS + wn * 64 + t * 16);
                int4 l0 = __ldg(lp);
                int4 l1 = __ldg(lp + 1);
                int4 l2 = __ldg(lp + 2);
                int4 l3 = __ldg(lp + 3);
                int l[16] = { l0.x, l0.y, l0.z, l0.w, l1.x, l1.y, l1.z, l1.w,
                              l2.x, l2.y, l2.z, l2.w, l3.x, l3.y, l3.z, l3.w };
                float sn = 0.0f, sp = 0.0f;
                #pragma unroll
                for (int ni = 0; ni < 8; ni++) {
                    __half2 p = *(__half2*)&acc[mi][ni][h];
                    float v0 = __low2float(p)  * SCALE_EX2;
                    float v1 = __high2float(p) * SCALE_EX2;
                    int lv0 = l[2 * ni];
                    int lv1 = l[2 * ni + 1];
                    float e0 = ex2(lv0 ? -v0 : v0);
                    float e1 = ex2(lv1 ? -v1 : v1);
                    if (lv0) sp += e0; else sn += e0;
                    if (lv1) sp += e1; else sn += e1;
                }
                sn += __shfl_xor_sync(0xFFFFFFFFu, sn, 1);
                sn += __shfl_xor_sync(0xFFFFFFFFu, sn, 2);
                sp += __shfl_xor_sync(0xFFFFFFFFu, sp, 1);
                sp += __shfl_xor_sync(0xFFFFFFFFu, sp, 2);
                if (t == 0) {
                    red_sn[wn * 128 + pixel] = sn;
                    red_sp[wn * 128 + pixel] = sp;
                }
            }
        }
        BARG(barid);

        float th_loss = 0.0f, th_cnt = 0.0f;
        if (tig < 128) {    // warps 0..3 of the group
            float tsn = red_sn[tig] + red_sn[128 + tig] + red_sn[256 + tig] + red_sn[384 + tig];
            float tsp = red_sp[tig] + red_sp[128 + tig] + red_sp[256 + tig] + red_sp[384 + tig];
            float loss = logf(tsn * tsp + 1.0f);
            th_loss = loss;
            th_cnt  = (loss != 0.0f) ? 1.0f : 0.0f;
            #pragma unroll
            for (int o = 16; o > 0; o >>= 1) {
                th_loss += __shfl_xor_sync(0xFFFFFFFFu, th_loss, o);
                th_cnt  += __shfl_xor_sync(0xFFFFFFFFu, th_cnt,  o);
            }
            if (lane == 0) {
                wpart[(tig >> 5) * 2]     = th_loss;
                wpart[(tig >> 5) * 2 + 1] = th_cnt;
            }
        }
        BARG(barid);
        if (tig == 0) {
            acc_s += (double)(wpart[0] + wpart[2] + wpart[4] + wpart[6]);
            acc_c += wpart[1] + wpart[3] + wpart[5] + wpart[7];
        }

        fbase = fbase_next;
    }

    // ---- publish per-group totals; last finishing group reduces ----
    if (tig == 0) {
        g_sum[gid] = acc_s;
        g_cnt[gid] = acc_c;
        __threadfence();
        unsigned old = atomicAdd(&g_done, 1u);
        s_last[g] = (old == NGROUPS - 1);
    }
    BARG(barid);

    if (s_last[g]) {
        double* dsum = (double*)(smem + 173184);          // 256 doubles
        float*  fcnt = (float*)(smem + 173184 + 2048);    // 256 floats
        double s = 0.0;
        float  c = 0.0f;
        #pragma unroll 1
        for (int i = tig; i < NGROUPS; i += 256) { s += g_sum[i]; c += g_cnt[i]; }
        dsum[tig] = s;
        fcnt[tig] = c;
        BARG(barid);
        for (int o = 128; o > 0; o >>= 1) {
            if (tig < o) { dsum[tig] += dsum[tig + o]; fcnt[tig] += fcnt[tig + o]; }
            BARG(barid);
        }
        if (tig == 0) {
            float cnt = fcnt[0];
            out[0] = (cnt == 0.0f) ? 0.0f : (float)(dsum[0] / (double)fmaxf(cnt, 1.0f));
            __threadfence();
            g_done = 0;   // reset for graph replay
        }
    }
}

extern "C" void kernel_launch(void* const* d_in, const int* in_sizes, int n_in,
                              void* d_out, int out_size)
{
    // metadata.txt order: feats (f32), queue (f32), labels (i32).
    // feats and labels have identical element counts — positional ID only.
    const float* feats  = (const float*)d_in[0];
    const float* queue  = (const float*)d_in[1];
    const int*   labels = (const int*)d_in[2];

    cudaFuncSetAttribute(pcl_main_kernel,
                         cudaFuncAttributeMaxDynamicSharedMemorySize, SMEM_BYTES);

    queue_to_f16_kernel<<<M_CLS * C_DIM / (2 * 256), 256>>>(queue);
    pcl_main_kernel<<<GRID, NTHREADS, SMEM_BYTES>>>(feats, labels, (float*)d_out);
}